// round 8
// baseline (speedup 1.0000x reference)
#include <cuda_runtime.h>

#define Bc 4
#define Lc 2048
#define Hc 8
#define Vc 64
#define HVc 512
#define NTHREADS 256

__device__ __forceinline__ float to_tf32(float x) {
    float r; asm("cvt.rna.tf32.f32 %0, %1;" : "=f"(r) : "f"(x)); return r;
}
// D += A(m16k8,row) * B(k8n8,col), tf32
__device__ __forceinline__ void mma8(float* d, const unsigned* a,
                                     unsigned b0, unsigned b1) {
    asm("mma.sync.aligned.m16n8k8.row.col.f32.tf32.tf32.f32 "
        "{%0,%1,%2,%3}, {%4,%5,%6,%7}, {%8,%9}, {%0,%1,%2,%3};"
        : "+f"(d[0]), "+f"(d[1]), "+f"(d[2]), "+f"(d[3])
        : "r"(a[0]), "r"(a[1]), "r"(a[2]), "r"(a[3]), "r"(b0), "r"(b1));
}

// ---- persistent device scratch ----
__device__ float g_att[Bc * Lc * HVc];          // normalized attended
__device__ float g_vb[Bc * 256 * 64 * 32 * 2];  // V in b-fragment order (tf32)
__device__ float g_wb[64 * 64 * 32 * 2];        // W in b-fragment order (tf32)
__device__ float g_kpos_c[Bc * Lc * 3];         // compacted key positions (pad=1000)
__device__ int   g_idx[Bc * Lc];
__device__ int   g_cnt[Bc];

// ================= compaction =================
__global__ void compact_kernel(const int* __restrict__ mask)
{
    const int b = blockIdx.x;
    const int lane = threadIdx.x;
    int cnt = 0;
    for (int k0 = 0; k0 < Lc; k0 += 32) {
        const int k = k0 + lane;
        const bool u = (mask[b * Lc + k] == 0);
        const unsigned bal = __ballot_sync(0xFFFFFFFFu, u);
        if (u) {
            const int pos = cnt + __popc(bal & ((1u << lane) - 1u));
            g_idx[b * Lc + pos] = k;
        }
        cnt += __popc(bal);
    }
    if (lane == 0) g_cnt[b] = cnt;
}

// ====== gather: values -> b-fragment layout (tf32), kpos compacted ======
__global__ void gather_kernel(const float* __restrict__ kpos,
                              const float* __restrict__ values)
{
    const int b  = blockIdx.x >> 5;
    const int j0 = (blockIdx.x & 31) * 64;
    const int tid = threadIdx.x;
    __shared__ int s_idx[64];
    __shared__ int s_n[2];

    if (tid == 0) { int c = g_cnt[b]; s_n[0] = c; s_n[1] = (c + 31) & ~31; }
    if (tid < 64 && j0 + tid < Lc) s_idx[tid] = g_idx[b * Lc + j0 + tid];
    __syncthreads();
    const int cnt = s_n[0];
    const int pad = s_n[1];
    const int jend = min(j0 + 64, pad);
    if (jend <= j0) return;
    const int nrows = jend - j0;

    const float4* v4 = (const float4*)values;
    for (int e = tid; e < nrows * 128; e += NTHREADS) {
        const int jl = e >> 7;
        const int c4 = e & 127;
        const int j  = j0 + jl;
        float4 v;
        if (j < cnt) v = v4[(size_t)(b * Lc + s_idx[jl]) * 128 + c4];
        else         v = make_float4(0.f, 0.f, 0.f, 0.f);
        v.x = to_tf32(v.x); v.y = to_tf32(v.y);
        v.z = to_tf32(v.z); v.w = to_tf32(v.w);
        const int ksg = j >> 3, kk = j & 7;
        const int tc = kk & 3, reg = kk >> 2;
        const float* pv = &v.x;
        #pragma unroll
        for (int t = 0; t < 4; t++) {
            const int c = c4 * 4 + t;
            const int h = c >> 6, n = (c >> 3) & 7, gr = c & 7;
            const size_t idx =
                ((((size_t)b * 256 + ksg) * 64 + h * 8 + n) * 32 + gr * 4 + tc) * 2 + reg;
            g_vb[idx] = pv[t];
        }
    }
    for (int e = tid; e < nrows * 3; e += NTHREADS) {
        const int jl = e / 3;
        const int d  = e % 3;
        const int j  = j0 + jl;
        float p = (j < cnt) ? kpos[(size_t)(b * Lc + s_idx[jl]) * 3 + d] : 1000.0f;
        g_kpos_c[(size_t)(b * Lc + j) * 3 + d] = p;
    }
}

// ====== W prepack: b-fragment order, tf32 ======
__global__ void prep_w(const float* __restrict__ W)
{
    const int p = blockIdx.x * 256 + threadIdx.x;   // float2 slot, 131072 total
    const int tc = p & 3;
    const int gr = (p >> 2) & 7;
    const int nb = (p >> 5) & 63;
    const int kb = p >> 11;
    const int row = nb * 8 + gr;
    const int col = kb * 8 + tc;
    g_wb[2 * p]     = to_tf32(W[row * HVc + col]);
    g_wb[2 * p + 1] = to_tf32(W[row * HVc + col + 4]);
}

// ============== attend: 64 queries x 4 heads per block, tf32 mma ==============
// 8 warps: hloc = warp>>1 (local head), nh = warp&1 (v-half). 4 m16 per warp.
__global__ __launch_bounds__(NTHREADS, 2)
void attend_kernel(const float* __restrict__ qpos,
                   const float* __restrict__ ls)
{
    __shared__ float s_S[4 * 2304];    // [hloc][q*36 + k], 64 q, stride 36
    __shared__ float s_kx[32], s_ky[32], s_kz[32];
    __shared__ float s_qp[192];
    __shared__ float s_ils[8];
    __shared__ float s_den[256];       // [hloc][q] -> 1/(den+eps)

    const int tid  = threadIdx.x;
    const int lane = tid & 31;
    const int warp = tid >> 5;
    const int gr = lane >> 2;
    const int tc = lane & 3;
    const int b  = blockIdx.x >> 6;
    const int qt = (blockIdx.x >> 1) & 31;
    const int hb = blockIdx.x & 1;

    if (tid < 192) s_qp[tid] = qpos[(b * Lc + qt * 64) * 3 + tid];
    if (tid < 8) { float l = ls[tid]; s_ils[tid] = 1.0f / (l * l); }
    __syncthreads();

    const int hloc = warp >> 1;
    const int nh   = warp & 1;
    const int head = hb * 4 + hloc;

    float rils[4];
    #pragma unroll
    for (int h = 0; h < 4; h++) rils[h] = s_ils[hb * 4 + h];

    const int nk_pad = (g_cnt[b] + 31) & ~31;

    float acc[4][4][4];
    float dacc[4][4];
    #pragma unroll
    for (int mt = 0; mt < 4; mt++) {
        #pragma unroll
        for (int nt = 0; nt < 4; nt++)
            #pragma unroll
            for (int r = 0; r < 4; r++) acc[mt][nt][r] = 0.0f;
        #pragma unroll
        for (int r = 0; r < 4; r++) dacc[mt][r] = 0.0f;
    }

    const unsigned bone = __float_as_uint(1.0f);
    const float2* vb2 = (const float2*)g_vb;

    for (int k0 = 0; k0 < nk_pad; k0 += 32) {
        __syncthreads();
        if (tid < 32) {
            const float* kp = g_kpos_c + (size_t)(b * Lc + k0 + tid) * 3;
            s_kx[tid] = kp[0];
            s_ky[tid] = kp[1];
            s_kz[tid] = kp[2];
        }
        __syncthreads();

        // phase A: 64q x 32k, 4 heads; d2 shared across heads
        #pragma unroll
        for (int j = 0; j < 8; j++) {
            const int p = tid + j * NTHREADS;
            const int q = p >> 5;           // warp-uniform
            const int k = p & 31;
            const float dx = s_qp[q * 3 + 0] - s_kx[k];
            const float dy = s_qp[q * 3 + 1] - s_ky[k];
            const float dz = s_qp[q * 3 + 2] - s_kz[k];
            const float d2 = dx * dx + dy * dy + dz * dz;
            float* sp = s_S + q * 36 + k;
            #pragma unroll
            for (int h = 0; h < 4; h++)
                sp[h * 2304] = to_tf32(__expf(-d2 * rils[h]));
        }
        __syncthreads();

        // mma phase
        const float* Sh = s_S + hloc * 2304;
        #pragma unroll
        for (int ks = 0; ks < 4; ks++) {
            const int kc = ks * 8 + tc;
            unsigned a[4][4];
            #pragma unroll
            for (int mt = 0; mt < 4; mt++) {
                a[mt][0] = __float_as_uint(Sh[(mt * 16 + gr)     * 36 + kc]);
                a[mt][1] = __float_as_uint(Sh[(mt * 16 + gr + 8) * 36 + kc]);
                a[mt][2] = __float_as_uint(Sh[(mt * 16 + gr)     * 36 + kc + 4]);
                a[mt][3] = __float_as_uint(Sh[(mt * 16 + gr + 8) * 36 + kc + 4]);
            }
            const size_t base =
                (((size_t)b * 256 + (k0 >> 3) + ks) * 64 + head * 8 + nh * 4) * 32 + lane;
            #pragma unroll
            for (int nt = 0; nt < 4; nt++) {
                const float2 bb = vb2[base + nt * 32];
                const unsigned b0 = __float_as_uint(bb.x);
                const unsigned b1 = __float_as_uint(bb.y);
                #pragma unroll
                for (int mt = 0; mt < 4; mt++)
                    mma8(acc[mt][nt], a[mt], b0, b1);
            }
            if (nh == 0) {
                #pragma unroll
                for (int mt = 0; mt < 4; mt++)
                    mma8(dacc[mt], a[mt], bone, bone);
            }
        }
    }

    // den share: even warp of each head pair publishes 1/(den+eps)
    if (nh == 0 && tc == 0) {
        #pragma unroll
        for (int mt = 0; mt < 4; mt++) {
            s_den[hloc * 64 + mt * 16 + gr]     = 1.0f / (dacc[mt][0] + 1e-5f);
            s_den[hloc * 64 + mt * 16 + gr + 8] = 1.0f / (dacc[mt][2] + 1e-5f);
        }
    }
    __syncthreads();

    #pragma unroll
    for (int mt = 0; mt < 4; mt++) {
        const float i0 = s_den[hloc * 64 + mt * 16 + gr];
        const float i1 = s_den[hloc * 64 + mt * 16 + gr + 8];
        const int q0 = qt * 64 + mt * 16 + gr;
        const size_t rb = (size_t)(b * Lc + q0) * HVc + head * 64 + nh * 32 + 2 * tc;
        #pragma unroll
        for (int nt = 0; nt < 4; nt++) {
            *(float2*)&g_att[rb + nt * 8] =
                make_float2(acc[mt][nt][0] * i0, acc[mt][nt][1] * i0);
            *(float2*)&g_att[rb + 8 * HVc + nt * 8] =
                make_float2(acc[mt][nt][2] * i1, acc[mt][nt][3] * i1);
        }
    }
}

// ====== projection: tf32 mma, 128x128 tile, W from g_wb fragments ======
#define ASTRIDE 20   // 16 k + pad 4 -> bank(m-frag) = (20*gr+tc)%32, all distinct

__global__ __launch_bounds__(256, 2)
void proj_kernel(float* __restrict__ out)
{
    __shared__ float As[128 * ASTRIDE];   // [m][k] for current 16-k chunk

    const int tid = threadIdx.x;
    const int lane = tid & 31;
    const int warp = tid >> 5;
    const int gr = lane >> 2;
    const int tc = lane & 3;
    const int wm = warp & 1;       // 2 m-halves of 64
    const int wn = warp >> 1;      // 4 n-quarters of 32
    const int m0 = blockIdx.y * 128;

    const int row0 = tid >> 2;           // 0..63
    const int row1 = 64 + row0;
    const int cg   = (tid & 3) * 4;      // k sub-group within chunk

    float acc[4][4][4];
    #pragma unroll
    for (int mt = 0; mt < 4; mt++)
        #pragma unroll
        for (int nt = 0; nt < 4; nt++)
            #pragma unroll
            for (int r = 0; r < 4; r++) acc[mt][nt][r] = 0.0f;

    const float4* att4 = (const float4*)g_att;
    const float2* wb2 = (const float2*)g_wb;

    // prefetch chunk 0
    float4 r0 = att4[(size_t)(m0 + row0) * 128 + (cg >> 2)];
    float4 r1 = att4[(size_t)(m0 + row1) * 128 + (cg >> 2)];

    for (int k0 = 0; k0 < HVc; k0 += 16) {
        As[row0 * ASTRIDE + cg + 0] = to_tf32(r0.x);
        As[row0 * ASTRIDE + cg + 1] = to_tf32(r0.y);
        As[row0 * ASTRIDE + cg + 2] = to_tf32(r0.z);
        As[row0 * ASTRIDE + cg + 3] = to_tf32(r0.w);
        As[row1 * ASTRIDE + cg + 0] = to_tf32(r1.x);
        As[row1 * ASTRIDE + cg + 1] = to_tf32(r1.y);
        As[row1 * ASTRIDE + cg + 2] = to_tf32(r1.z);
        As[row1 * ASTRIDE + cg + 3] = to_tf32(r1.w);
        __syncthreads();

        if (k0 + 16 < HVc) {
            const int kn = (k0 + 16 + cg) >> 2;
            r0 = att4[(size_t)(m0 + row0) * 128 + kn];
            r1 = att4[(size_t)(m0 + row1) * 128 + kn];
        }

        #pragma unroll
        for (int kk = 0; kk < 2; kk++) {
            const int kc = kk * 8 + tc;
            unsigned a[4][4];
            #pragma unroll
            for (int mt = 0; mt < 4; mt++) {
                const int mr = wm * 64 + mt * 16 + gr;
                a[mt][0] = __float_as_uint(As[mr * ASTRIDE + kc]);
                a[mt][1] = __float_as_uint(As[(mr + 8) * ASTRIDE + kc]);
                a[mt][2] = __float_as_uint(As[mr * ASTRIDE + kc + 4]);
                a[mt][3] = __float_as_uint(As[(mr + 8) * ASTRIDE + kc + 4]);
            }
            const int kb = (k0 >> 3) + kk;
            const int nbase = blockIdx.x * 16 + wn * 4;
            #pragma unroll
            for (int nt = 0; nt < 4; nt++) {
                const float2 bb = wb2[(size_t)(kb * 64 + nbase + nt) * 32 + lane];
                const unsigned b0 = __float_as_uint(bb.x);
                const unsigned b1 = __float_as_uint(bb.y);
                #pragma unroll
                for (int mt = 0; mt < 4; mt++)
                    mma8(acc[mt][nt], a[mt], b0, b1);
            }
        }
        __syncthreads();
    }

    const int n0 = blockIdx.x * 128;
    #pragma unroll
    for (int mt = 0; mt < 4; mt++) {
        const int row = m0 + wm * 64 + mt * 16 + gr;
        #pragma unroll
        for (int nt = 0; nt < 4; nt++) {
            const int col = n0 + wn * 32 + nt * 8 + 2 * tc;
            *(float2*)&out[(size_t)row * HVc + col] =
                make_float2(acc[mt][nt][0], acc[mt][nt][1]);
            *(float2*)&out[(size_t)(row + 8) * HVc + col] =
                make_float2(acc[mt][nt][2], acc[mt][nt][3]);
        }
    }
}

extern "C" void kernel_launch(void* const* d_in, const int* in_sizes, int n_in,
                              void* d_out, int out_size)
{
    const float* qpos   = (const float*)d_in[0];
    const float* kpos   = (const float*)d_in[1];
    const float* values = (const float*)d_in[2];
    const int*   mask   = (const int*)  d_in[3];
    const float* ls     = (const float*)d_in[4];
    const float* w_out  = (const float*)d_in[5];
    float* out = (float*)d_out;

    compact_kernel<<<Bc, 32>>>(mask);
    gather_kernel<<<Bc * 32, NTHREADS>>>(kpos, values);
    prep_w<<<512, 256>>>(w_out);
    attend_kernel<<<Bc * 32 * 2, NTHREADS>>>(qpos, ls);
    proj_kernel<<<dim3(HVc / 128, (Bc * Lc) / 128), 256>>>(out);
}

// round 9
// speedup vs baseline: 1.4762x; 1.4762x over previous
#include <cuda_runtime.h>

#define Bc 4
#define Lc 2048
#define Hc 8
#define Vc 64
#define HVc 512
#define NTHREADS 256

__device__ __forceinline__ float to_tf32(float x) {
    float r; asm("cvt.rna.tf32.f32 %0, %1;" : "=f"(r) : "f"(x)); return r;
}
// D += A(m16k8,row) * B(k8n8,col), tf32
__device__ __forceinline__ void mma8(float* d, const unsigned* a,
                                     unsigned b0, unsigned b1) {
    asm("mma.sync.aligned.m16n8k8.row.col.f32.tf32.tf32.f32 "
        "{%0,%1,%2,%3}, {%4,%5,%6,%7}, {%8,%9}, {%0,%1,%2,%3};"
        : "+f"(d[0]), "+f"(d[1]), "+f"(d[2]), "+f"(d[3])
        : "r"(a[0]), "r"(a[1]), "r"(a[2]), "r"(a[3]), "r"(b0), "r"(b1));
}

// ---- persistent device scratch ----
__device__ float g_att[Bc * Lc * HVc];          // normalized attended
__device__ float g_vb[Bc * 256 * 64 * 32 * 2];  // V in b-fragment order (tf32)
__device__ float g_wb[64 * 64 * 32 * 2];        // W in b-fragment order (tf32)
__device__ float g_kpos_c[Bc * Lc * 3];         // compacted key positions (pad=1000)
__device__ int   g_idx[Bc * Lc];
__device__ int   g_cnt[Bc];

// ================= compaction =================
__global__ void compact_kernel(const int* __restrict__ mask)
{
    const int b = blockIdx.x;
    const int lane = threadIdx.x;
    int cnt = 0;
    for (int k0 = 0; k0 < Lc; k0 += 32) {
        const int k = k0 + lane;
        const bool u = (mask[b * Lc + k] == 0);
        const unsigned bal = __ballot_sync(0xFFFFFFFFu, u);
        if (u) {
            const int pos = cnt + __popc(bal & ((1u << lane) - 1u));
            g_idx[b * Lc + pos] = k;
        }
        cnt += __popc(bal);
    }
    if (lane == 0) g_cnt[b] = cnt;
}

// ====== gather: values -> b-fragment layout (tf32), kpos compacted ======
__global__ void gather_kernel(const float* __restrict__ kpos,
                              const float* __restrict__ values)
{
    const int b  = blockIdx.x >> 5;
    const int j0 = (blockIdx.x & 31) * 64;
    const int tid = threadIdx.x;
    __shared__ int s_idx[64];
    __shared__ int s_n[2];

    if (tid == 0) { int c = g_cnt[b]; s_n[0] = c; s_n[1] = (c + 31) & ~31; }
    if (tid < 64 && j0 + tid < Lc) s_idx[tid] = g_idx[b * Lc + j0 + tid];
    __syncthreads();
    const int cnt = s_n[0];
    const int pad = s_n[1];
    const int jend = min(j0 + 64, pad);
    if (jend <= j0) return;
    const int nrows = jend - j0;

    const float4* v4 = (const float4*)values;
    for (int e = tid; e < nrows * 128; e += NTHREADS) {
        const int jl = e >> 7;
        const int c4 = e & 127;
        const int j  = j0 + jl;
        float4 v;
        if (j < cnt) v = v4[(size_t)(b * Lc + s_idx[jl]) * 128 + c4];
        else         v = make_float4(0.f, 0.f, 0.f, 0.f);
        v.x = to_tf32(v.x); v.y = to_tf32(v.y);
        v.z = to_tf32(v.z); v.w = to_tf32(v.w);
        const int ksg = j >> 3, kk = j & 7;
        const int tc = kk & 3, reg = kk >> 2;
        const float* pv = &v.x;
        #pragma unroll
        for (int t = 0; t < 4; t++) {
            const int c = c4 * 4 + t;
            const int h = c >> 6, n = (c >> 3) & 7, gr = c & 7;
            const size_t idx =
                ((((size_t)b * 256 + ksg) * 64 + h * 8 + n) * 32 + gr * 4 + tc) * 2 + reg;
            g_vb[idx] = pv[t];
        }
    }
    for (int e = tid; e < nrows * 3; e += NTHREADS) {
        const int jl = e / 3;
        const int d  = e % 3;
        const int j  = j0 + jl;
        float p = (j < cnt) ? kpos[(size_t)(b * Lc + s_idx[jl]) * 3 + d] : 1000.0f;
        g_kpos_c[(size_t)(b * Lc + j) * 3 + d] = p;
    }
}

// ====== W prepack: b-fragment order, tf32 ======
__global__ void prep_w(const float* __restrict__ W)
{
    const int p = blockIdx.x * 256 + threadIdx.x;   // float2 slot
    const int tc = p & 3;
    const int gr = (p >> 2) & 7;
    const int nb = (p >> 5) & 63;
    const int kb = p >> 11;
    const int row = nb * 8 + gr;
    const int col = kb * 8 + tc;
    g_wb[2 * p]     = to_tf32(W[row * HVc + col]);
    g_wb[2 * p + 1] = to_tf32(W[row * HVc + col + 4]);
}

// ======= attend (R7 structure): 32 queries x 8 heads; warp = head =======
__global__ __launch_bounds__(NTHREADS, 2)
void attend_kernel(const float* __restrict__ qpos,
                   const float* __restrict__ ls)
{
    __shared__ float s_S[8 * 1152];   // [h][q*36 + k]
    __shared__ float s_kx[32], s_ky[32], s_kz[32];
    __shared__ float s_qp[96];
    __shared__ float s_ils[8];

    const int tid  = threadIdx.x;
    const int lane = tid & 31;
    const int warp = tid >> 5;
    const int gr = lane >> 2;
    const int tc = lane & 3;
    const int b  = blockIdx.x >> 6;
    const int qt = blockIdx.x & 63;

    if (tid < 96) s_qp[tid] = qpos[(b * Lc + qt * 32) * 3 + tid];
    if (tid < 8) { float l = ls[tid]; s_ils[tid] = 1.0f / (l * l); }
    __syncthreads();

    // phase-A persona: q = gr + 8*(warp&3), k-half = (warp>>2)
    const int qa = gr + 8 * (warp & 3);
    const int kK = (warp >> 2) * 16;
    const float qx = s_qp[qa * 3 + 0];
    const float qy = s_qp[qa * 3 + 1];
    const float qz = s_qp[qa * 3 + 2];
    float rils[8];
    #pragma unroll
    for (int h = 0; h < 8; h++) rils[h] = s_ils[h];

    const int nk_pad = (g_cnt[b] + 31) & ~31;

    float acc[2][8][4];
    float dacc[2][4];
    #pragma unroll
    for (int m = 0; m < 2; m++) {
        #pragma unroll
        for (int n = 0; n < 8; n++)
            #pragma unroll
            for (int r = 0; r < 4; r++) acc[m][n][r] = 0.0f;
        #pragma unroll
        for (int r = 0; r < 4; r++) dacc[m][r] = 0.0f;
    }

    const unsigned bone = __float_as_uint(1.0f);
    const float2* vb2 = (const float2*)g_vb;

    for (int k0 = 0; k0 < nk_pad; k0 += 32) {
        __syncthreads();
        if (tid < 32) {
            const float* kp = g_kpos_c + (size_t)(b * Lc + k0 + tid) * 3;
            s_kx[tid] = kp[0];
            s_ky[tid] = kp[1];
            s_kz[tid] = kp[2];
        }
        __syncthreads();

        // phase A: S[h][q][k] = tf32(exp(-d2/ls^2)); d2 shared across heads
        #pragma unroll
        for (int j = 0; j < 4; j++) {
            const int k = kK + tc + 4 * j;
            const float dx = qx - s_kx[k];
            const float dy = qy - s_ky[k];
            const float dz = qz - s_kz[k];
            const float d2 = dx * dx + dy * dy + dz * dz;
            float* sp = s_S + qa * 36 + k;
            #pragma unroll
            for (int h = 0; h < 8; h++)
                sp[h * 1152] = to_tf32(__expf(-d2 * rils[h]));
        }
        __syncthreads();

        // mma phase: warp = head
        const float* Sh = s_S + warp * 1152;
        const size_t vbase =
            (((size_t)b * 256 + (k0 >> 3)) * 64 + warp * 8) * 32 + lane;
        #pragma unroll
        for (int ks = 0; ks < 4; ks++) {
            const int kc = ks * 8 + tc;
            unsigned a0[4], a1[4];
            a0[0] = __float_as_uint(Sh[(gr)      * 36 + kc]);
            a0[1] = __float_as_uint(Sh[(gr + 8)  * 36 + kc]);
            a0[2] = __float_as_uint(Sh[(gr)      * 36 + kc + 4]);
            a0[3] = __float_as_uint(Sh[(gr + 8)  * 36 + kc + 4]);
            a1[0] = __float_as_uint(Sh[(gr + 16) * 36 + kc]);
            a1[1] = __float_as_uint(Sh[(gr + 24) * 36 + kc]);
            a1[2] = __float_as_uint(Sh[(gr + 16) * 36 + kc + 4]);
            a1[3] = __float_as_uint(Sh[(gr + 24) * 36 + kc + 4]);
            const float2* vp = vb2 + vbase + (size_t)ks * (64 * 32);
            #pragma unroll
            for (int n = 0; n < 8; n++) {
                const float2 bb = vp[n * 32];
                const unsigned b0 = __float_as_uint(bb.x);
                const unsigned b1 = __float_as_uint(bb.y);
                mma8(acc[0][n], a0, b0, b1);
                mma8(acc[1][n], a1, b0, b1);
            }
            mma8(dacc[0], a0, bone, bone);
            mma8(dacc[1], a1, bone, bone);
        }
    }

    // epilogue: each thread holds den for exactly its 4 output rows
    #pragma unroll
    for (int m = 0; m < 2; m++) {
        const float i0 = 1.0f / (dacc[m][0] + 1e-5f);   // row gr
        const float i1 = 1.0f / (dacc[m][2] + 1e-5f);   // row gr+8
        const int q0 = qt * 32 + m * 16 + gr;
        const size_t rb = (size_t)(b * Lc + q0) * HVc + warp * 64 + 2 * tc;
        #pragma unroll
        for (int n = 0; n < 8; n++) {
            *(float2*)&g_att[rb + n * 8] =
                make_float2(acc[m][n][0] * i0, acc[m][n][1] * i0);
            *(float2*)&g_att[rb + 8 * HVc + n * 8] =
                make_float2(acc[m][n][2] * i1, acc[m][n][3] * i1);
        }
    }
}

// ====== projection (R8): tf32 mma, 128x128 tile, W from g_wb fragments ======
#define ASTRIDE 20   // 16 k + pad 4 -> bank(m-frag) = (20*gr+tc)%32, all distinct

__global__ __launch_bounds__(256, 2)
void proj_kernel(float* __restrict__ out)
{
    __shared__ float As[128 * ASTRIDE];   // [m][k] for current 16-k chunk

    const int tid = threadIdx.x;
    const int lane = tid & 31;
    const int warp = tid >> 5;
    const int gr = lane >> 2;
    const int tc = lane & 3;
    const int wm = warp & 1;       // 2 m-halves of 64
    const int wn = warp >> 1;      // 4 n-quarters of 32
    const int m0 = blockIdx.y * 128;

    const int row0 = tid >> 2;           // 0..63
    const int row1 = 64 + row0;
    const int cg   = (tid & 3) * 4;      // k sub-group within chunk

    float acc[4][4][4];
    #pragma unroll
    for (int mt = 0; mt < 4; mt++)
        #pragma unroll
        for (int nt = 0; nt < 4; nt++)
            #pragma unroll
            for (int r = 0; r < 4; r++) acc[mt][nt][r] = 0.0f;

    const float4* att4 = (const float4*)g_att;
    const float2* wb2 = (const float2*)g_wb;

    float4 r0 = att4[(size_t)(m0 + row0) * 128 + (cg >> 2)];
    float4 r1 = att4[(size_t)(m0 + row1) * 128 + (cg >> 2)];

    for (int k0 = 0; k0 < HVc; k0 += 16) {
        As[row0 * ASTRIDE + cg + 0] = to_tf32(r0.x);
        As[row0 * ASTRIDE + cg + 1] = to_tf32(r0.y);
        As[row0 * ASTRIDE + cg + 2] = to_tf32(r0.z);
        As[row0 * ASTRIDE + cg + 3] = to_tf32(r0.w);
        As[row1 * ASTRIDE + cg + 0] = to_tf32(r1.x);
        As[row1 * ASTRIDE + cg + 1] = to_tf32(r1.y);
        As[row1 * ASTRIDE + cg + 2] = to_tf32(r1.z);
        As[row1 * ASTRIDE + cg + 3] = to_tf32(r1.w);
        __syncthreads();

        if (k0 + 16 < HVc) {
            const int kn = (k0 + 16 + cg) >> 2;
            r0 = att4[(size_t)(m0 + row0) * 128 + kn];
            r1 = att4[(size_t)(m0 + row1) * 128 + kn];
        }

        #pragma unroll
        for (int kk = 0; kk < 2; kk++) {
            const int kc = kk * 8 + tc;
            unsigned a[4][4];
            #pragma unroll
            for (int mt = 0; mt < 4; mt++) {
                const int mr = wm * 64 + mt * 16 + gr;
                a[mt][0] = __float_as_uint(As[mr * ASTRIDE + kc]);
                a[mt][1] = __float_as_uint(As[(mr + 8) * ASTRIDE + kc]);
                a[mt][2] = __float_as_uint(As[mr * ASTRIDE + kc + 4]);
                a[mt][3] = __float_as_uint(As[(mr + 8) * ASTRIDE + kc + 4]);
            }
            const int kb = (k0 >> 3) + kk;
            const int nbase = blockIdx.x * 16 + wn * 4;
            #pragma unroll
            for (int nt = 0; nt < 4; nt++) {
                const float2 bb = wb2[(size_t)(kb * 64 + nbase + nt) * 32 + lane];
                const unsigned b0 = __float_as_uint(bb.x);
                const unsigned b1 = __float_as_uint(bb.y);
                #pragma unroll
                for (int mt = 0; mt < 4; mt++)
                    mma8(acc[mt][nt], a[mt], b0, b1);
            }
        }
        __syncthreads();
    }

    const int n0 = blockIdx.x * 128;
    #pragma unroll
    for (int mt = 0; mt < 4; mt++) {
        const int row = m0 + wm * 64 + mt * 16 + gr;
        #pragma unroll
        for (int nt = 0; nt < 4; nt++) {
            const int col = n0 + wn * 32 + nt * 8 + 2 * tc;
            *(float2*)&out[(size_t)row * HVc + col] =
                make_float2(acc[mt][nt][0], acc[mt][nt][1]);
            *(float2*)&out[(size_t)(row + 8) * HVc + col] =
                make_float2(acc[mt][nt][2], acc[mt][nt][3]);
        }
    }
}

extern "C" void kernel_launch(void* const* d_in, const int* in_sizes, int n_in,
                              void* d_out, int out_size)
{
    const float* qpos   = (const float*)d_in[0];
    const float* kpos   = (const float*)d_in[1];
    const float* values = (const float*)d_in[2];
    const int*   mask   = (const int*)  d_in[3];
    const float* ls     = (const float*)d_in[4];
    const float* w_out  = (const float*)d_in[5];
    float* out = (float*)d_out;

    compact_kernel<<<Bc, 32>>>(mask);
    gather_kernel<<<Bc * 32, NTHREADS>>>(kpos, values);
    prep_w<<<512, 256>>>(w_out);
    attend_kernel<<<Bc * (Lc / 32), NTHREADS>>>(qpos, ls);
    proj_kernel<<<dim3(HVc / 128, (Bc * Lc) / 128), 256>>>(out);
}

// round 10
// speedup vs baseline: 1.6532x; 1.1199x over previous
#include <cuda_runtime.h>

#define Bc 4
#define Lc 2048
#define Hc 8
#define Vc 64
#define HVc 512
#define NTHREADS 256

__device__ __forceinline__ float to_tf32(float x) {
    float r; asm("cvt.rna.tf32.f32 %0, %1;" : "=f"(r) : "f"(x)); return r;
}
// D += A(m16k8,row) * B(k8n8,col), tf32
__device__ __forceinline__ void mma8(float* d, const unsigned* a,
                                     unsigned b0, unsigned b1) {
    asm("mma.sync.aligned.m16n8k8.row.col.f32.tf32.tf32.f32 "
        "{%0,%1,%2,%3}, {%4,%5,%6,%7}, {%8,%9}, {%0,%1,%2,%3};"
        : "+f"(d[0]), "+f"(d[1]), "+f"(d[2]), "+f"(d[3])
        : "r"(a[0]), "r"(a[1]), "r"(a[2]), "r"(a[3]), "r"(b0), "r"(b1));
}

// ---- persistent device scratch ----
__device__ float g_att[Bc * Lc * HVc];          // normalized attended
__device__ float g_vb[Bc * 256 * 64 * 32 * 2];  // V in b-fragment order (tf32)
__device__ float g_wb[64 * 64 * 32 * 2];        // W in b-fragment order (tf32)
__device__ float g_kpos_c[Bc * Lc * 3];         // compacted key positions (pad=1000)
__device__ int   g_idx[Bc * Lc];
__device__ int   g_cnt[Bc];

// ================= compaction =================
__global__ void compact_kernel(const int* __restrict__ mask)
{
    const int b = blockIdx.x;
    const int lane = threadIdx.x;
    int cnt = 0;
    for (int k0 = 0; k0 < Lc; k0 += 32) {
        const int k = k0 + lane;
        const bool u = (mask[b * Lc + k] == 0);
        const unsigned bal = __ballot_sync(0xFFFFFFFFu, u);
        if (u) {
            const int pos = cnt + __popc(bal & ((1u << lane) - 1u));
            g_idx[b * Lc + pos] = k;
        }
        cnt += __popc(bal);
    }
    if (lane == 0) g_cnt[b] = cnt;
}

// ====== gather: values -> b-fragment layout (tf32), kpos compacted ======
__global__ void gather_kernel(const float* __restrict__ kpos,
                              const float* __restrict__ values)
{
    const int b  = blockIdx.x >> 5;
    const int j0 = (blockIdx.x & 31) * 64;
    const int tid = threadIdx.x;
    __shared__ int s_idx[64];
    __shared__ int s_n[2];

    if (tid == 0) { int c = g_cnt[b]; s_n[0] = c; s_n[1] = (c + 31) & ~31; }
    if (tid < 64 && j0 + tid < Lc) s_idx[tid] = g_idx[b * Lc + j0 + tid];
    __syncthreads();
    const int cnt = s_n[0];
    const int pad = s_n[1];
    const int jend = min(j0 + 64, pad);
    if (jend <= j0) return;
    const int nrows = jend - j0;

    const float4* v4 = (const float4*)values;
    for (int e = tid; e < nrows * 128; e += NTHREADS) {
        const int jl = e >> 7;
        const int c4 = e & 127;
        const int j  = j0 + jl;
        float4 v;
        if (j < cnt) v = v4[(size_t)(b * Lc + s_idx[jl]) * 128 + c4];
        else         v = make_float4(0.f, 0.f, 0.f, 0.f);
        v.x = to_tf32(v.x); v.y = to_tf32(v.y);
        v.z = to_tf32(v.z); v.w = to_tf32(v.w);
        const int ksg = j >> 3, kk = j & 7;
        const int tc = kk & 3, reg = kk >> 2;
        const float* pv = &v.x;
        #pragma unroll
        for (int t = 0; t < 4; t++) {
            const int c = c4 * 4 + t;
            const int h = c >> 6, n = (c >> 3) & 7, gr = c & 7;
            const size_t idx =
                ((((size_t)b * 256 + ksg) * 64 + h * 8 + n) * 32 + gr * 4 + tc) * 2 + reg;
            g_vb[idx] = pv[t];
        }
    }
    for (int e = tid; e < nrows * 3; e += NTHREADS) {
        const int jl = e / 3;
        const int d  = e % 3;
        const int j  = j0 + jl;
        float p = (j < cnt) ? kpos[(size_t)(b * Lc + s_idx[jl]) * 3 + d] : 1000.0f;
        g_kpos_c[(size_t)(b * Lc + j) * 3 + d] = p;
    }
}

// ====== W prepack: b-fragment order, tf32 ======
__global__ void prep_w(const float* __restrict__ W)
{
    const int p = blockIdx.x * 256 + threadIdx.x;   // float2 slot
    const int tc = p & 3;
    const int gr = (p >> 2) & 7;
    const int nb = (p >> 5) & 63;
    const int kb = p >> 11;
    const int row = nb * 8 + gr;
    const int col = kb * 8 + tc;
    g_wb[2 * p]     = to_tf32(W[row * HVc + col]);
    g_wb[2 * p + 1] = to_tf32(W[row * HVc + col + 4]);
}

// ======= attend: 32q x 8h, warp = head; pipelined, 1 barrier per tile =======
// dynamic smem layout (floats):
//  s_S:  [0, 18432)   two buffers of [h][q*36+k] (9216 each)
//  s_k:  [18432, 18624)  two buffers of kx[32]|ky[32]|kz[32] (96 each)
//  s_qp: [18624, 18720)
//  s_ils:[18720, 18728)
#define AOFF_S   0
#define AOFF_K   18432
#define AOFF_QP  18624
#define AOFF_ILS 18720
#define ASMEM_FLOATS 18728

__global__ __launch_bounds__(NTHREADS, 2)
void attend_kernel(const float* __restrict__ qpos,
                   const float* __restrict__ ls)
{
    extern __shared__ float sm[];
    float* s_S  = sm + AOFF_S;
    float* s_k  = sm + AOFF_K;
    float* s_qp = sm + AOFF_QP;
    float* s_ils = sm + AOFF_ILS;

    const int tid  = threadIdx.x;
    const int lane = tid & 31;
    const int warp = tid >> 5;
    const int gr = lane >> 2;
    const int tc = lane & 3;
    const int b  = blockIdx.x >> 6;
    const int qt = blockIdx.x & 63;

    if (tid < 96) s_qp[tid] = qpos[(b * Lc + qt * 32) * 3 + tid];
    if (tid < 8) { float l = ls[tid]; s_ils[tid] = 1.0f / (l * l); }

    const int nk_pad = (g_cnt[b] + 31) & ~31;
    const int nt = nk_pad >> 5;

    // prologue: kpos tile 0
    if (tid < 32) {
        const float* kp = g_kpos_c + (size_t)(b * Lc + tid) * 3;
        s_k[tid] = kp[0]; s_k[32 + tid] = kp[1]; s_k[64 + tid] = kp[2];
    }
    __syncthreads();

    // phase-A persona: q = gr + 8*(warp&3), k-half = (warp>>2)
    const int qa = gr + 8 * (warp & 3);
    const int kK = (warp >> 2) * 16;
    const float qx = s_qp[qa * 3 + 0];
    const float qy = s_qp[qa * 3 + 1];
    const float qz = s_qp[qa * 3 + 2];
    float rils[8];
    #pragma unroll
    for (int h = 0; h < 8; h++) rils[h] = s_ils[h];

    // phase A tile 0 -> s_S[0]; kpos tile 1 -> s_k[1]
    if (tid < 32 && nt > 1) {
        const float* kp = g_kpos_c + (size_t)(b * Lc + 32 + tid) * 3;
        s_k[96 + tid] = kp[0]; s_k[96 + 32 + tid] = kp[1]; s_k[96 + 64 + tid] = kp[2];
    }
    {
        #pragma unroll
        for (int j = 0; j < 4; j++) {
            const int k = kK + tc + 4 * j;
            const float dx = qx - s_k[k];
            const float dy = qy - s_k[32 + k];
            const float dz = qz - s_k[64 + k];
            const float d2 = dx * dx + dy * dy + dz * dz;
            float* sp = s_S + qa * 36 + k;
            #pragma unroll
            for (int h = 0; h < 8; h++)
                sp[h * 1152] = to_tf32(__expf(-d2 * rils[h]));
        }
    }
    __syncthreads();

    float acc[2][8][4];
    float dacc[2][4];
    #pragma unroll
    for (int m = 0; m < 2; m++) {
        #pragma unroll
        for (int n = 0; n < 8; n++)
            #pragma unroll
            for (int r = 0; r < 4; r++) acc[m][n][r] = 0.0f;
        #pragma unroll
        for (int r = 0; r < 4; r++) dacc[m][r] = 0.0f;
    }

    const unsigned bone = __float_as_uint(1.0f);
    const float2* vb2 = (const float2*)g_vb;

    for (int t = 0; t < nt; t++) {
        const int cur = t & 1;
        const int nxt = cur ^ 1;

        // 1) early LDG: kpos for tile t+2 (consumed at step 4)
        float px = 0.f, py = 0.f, pz = 0.f;
        const bool havep = (tid < 32) && (t + 2 < nt);
        if (havep) {
            const float* kp = g_kpos_c + (size_t)(b * Lc + (t + 2) * 32 + tid) * 3;
            px = kp[0]; py = kp[1]; pz = kp[2];
        }

        // 2) phase A for tile t+1 -> s_S[nxt] (from s_k[nxt])
        if (t + 1 < nt) {
            const float* kb_ = s_k + nxt * 96;
            float* Sn = s_S + nxt * 9216;
            #pragma unroll
            for (int j = 0; j < 4; j++) {
                const int k = kK + tc + 4 * j;
                const float dx = qx - kb_[k];
                const float dy = qy - kb_[32 + k];
                const float dz = qz - kb_[64 + k];
                const float d2 = dx * dx + dy * dy + dz * dz;
                float* sp = Sn + qa * 36 + k;
                #pragma unroll
                for (int h = 0; h < 8; h++)
                    sp[h * 1152] = to_tf32(__expf(-d2 * rils[h]));
            }
        }

        // 3) mma for tile t from s_S[cur]
        {
            const float* Sh = s_S + cur * 9216 + warp * 1152;
            const size_t vbase =
                (((size_t)b * 256 + t * 4) * 64 + warp * 8) * 32 + lane;
            #pragma unroll
            for (int ks = 0; ks < 4; ks++) {
                const int kc = ks * 8 + tc;
                unsigned a0[4], a1[4];
                a0[0] = __float_as_uint(Sh[(gr)      * 36 + kc]);
                a0[1] = __float_as_uint(Sh[(gr + 8)  * 36 + kc]);
                a0[2] = __float_as_uint(Sh[(gr)      * 36 + kc + 4]);
                a0[3] = __float_as_uint(Sh[(gr + 8)  * 36 + kc + 4]);
                a1[0] = __float_as_uint(Sh[(gr + 16) * 36 + kc]);
                a1[1] = __float_as_uint(Sh[(gr + 24) * 36 + kc]);
                a1[2] = __float_as_uint(Sh[(gr + 16) * 36 + kc + 4]);
                a1[3] = __float_as_uint(Sh[(gr + 24) * 36 + kc + 4]);
                const float2* vp = vb2 + vbase + (size_t)ks * (64 * 32);
                #pragma unroll
                for (int n = 0; n < 8; n++) {
                    const float2 bb = vp[n * 32];
                    const unsigned b0 = __float_as_uint(bb.x);
                    const unsigned b1 = __float_as_uint(bb.y);
                    mma8(acc[0][n], a0, b0, b1);
                    mma8(acc[1][n], a1, b0, b1);
                }
                mma8(dacc[0], a0, bone, bone);
                mma8(dacc[1], a1, bone, bone);
            }
        }

        // 4) park kpos(t+2) into s_k[cur] (tile t's kpos no longer needed)
        if (havep) {
            float* kd = s_k + cur * 96;
            kd[tid] = px; kd[32 + tid] = py; kd[64 + tid] = pz;
        }

        // 5) single barrier
        __syncthreads();
    }

    // epilogue: each thread holds den for exactly its 4 output rows
    #pragma unroll
    for (int m = 0; m < 2; m++) {
        const float i0 = 1.0f / (dacc[m][0] + 1e-5f);   // row gr
        const float i1 = 1.0f / (dacc[m][2] + 1e-5f);   // row gr+8
        const int q0 = qt * 32 + m * 16 + gr;
        const size_t rb = (size_t)(b * Lc + q0) * HVc + warp * 64 + 2 * tc;
        #pragma unroll
        for (int n = 0; n < 8; n++) {
            *(float2*)&g_att[rb + n * 8] =
                make_float2(acc[m][n][0] * i0, acc[m][n][1] * i0);
            *(float2*)&g_att[rb + 8 * HVc + n * 8] =
                make_float2(acc[m][n][2] * i1, acc[m][n][3] * i1);
        }
    }
}

// ====== projection (R8): tf32 mma, 128x128 tile, W from g_wb fragments ======
#define ASTRIDE 20   // 16 k + pad 4 -> bank(m-frag) = (20*gr+tc)%32, all distinct

__global__ __launch_bounds__(256, 2)
void proj_kernel(float* __restrict__ out)
{
    __shared__ float As[128 * ASTRIDE];   // [m][k] for current 16-k chunk

    const int tid = threadIdx.x;
    const int lane = tid & 31;
    const int warp = tid >> 5;
    const int gr = lane >> 2;
    const int tc = lane & 3;
    const int wm = warp & 1;       // 2 m-halves of 64
    const int wn = warp >> 1;      // 4 n-quarters of 32
    const int m0 = blockIdx.y * 128;

    const int row0 = tid >> 2;           // 0..63
    const int row1 = 64 + row0;
    const int cg   = (tid & 3) * 4;      // k sub-group within chunk

    float acc[4][4][4];
    #pragma unroll
    for (int mt = 0; mt < 4; mt++)
        #pragma unroll
        for (int nt = 0; nt < 4; nt++)
            #pragma unroll
            for (int r = 0; r < 4; r++) acc[mt][nt][r] = 0.0f;

    const float4* att4 = (const float4*)g_att;
    const float2* wb2 = (const float2*)g_wb;

    float4 r0 = att4[(size_t)(m0 + row0) * 128 + (cg >> 2)];
    float4 r1 = att4[(size_t)(m0 + row1) * 128 + (cg >> 2)];

    for (int k0 = 0; k0 < HVc; k0 += 16) {
        As[row0 * ASTRIDE + cg + 0] = to_tf32(r0.x);
        As[row0 * ASTRIDE + cg + 1] = to_tf32(r0.y);
        As[row0 * ASTRIDE + cg + 2] = to_tf32(r0.z);
        As[row0 * ASTRIDE + cg + 3] = to_tf32(r0.w);
        As[row1 * ASTRIDE + cg + 0] = to_tf32(r1.x);
        As[row1 * ASTRIDE + cg + 1] = to_tf32(r1.y);
        As[row1 * ASTRIDE + cg + 2] = to_tf32(r1.z);
        As[row1 * ASTRIDE + cg + 3] = to_tf32(r1.w);
        __syncthreads();

        if (k0 + 16 < HVc) {
            const int kn = (k0 + 16 + cg) >> 2;
            r0 = att4[(size_t)(m0 + row0) * 128 + kn];
            r1 = att4[(size_t)(m0 + row1) * 128 + kn];
        }

        #pragma unroll
        for (int kk = 0; kk < 2; kk++) {
            const int kc = kk * 8 + tc;
            unsigned a[4][4];
            #pragma unroll
            for (int mt = 0; mt < 4; mt++) {
                const int mr = wm * 64 + mt * 16 + gr;
                a[mt][0] = __float_as_uint(As[mr * ASTRIDE + kc]);
                a[mt][1] = __float_as_uint(As[(mr + 8) * ASTRIDE + kc]);
                a[mt][2] = __float_as_uint(As[mr * ASTRIDE + kc + 4]);
                a[mt][3] = __float_as_uint(As[(mr + 8) * ASTRIDE + kc + 4]);
            }
            const int kb = (k0 >> 3) + kk;
            const int nbase = blockIdx.x * 16 + wn * 4;
            #pragma unroll
            for (int nt = 0; nt < 4; nt++) {
                const float2 bb = wb2[(size_t)(kb * 64 + nbase + nt) * 32 + lane];
                const unsigned b0 = __float_as_uint(bb.x);
                const unsigned b1 = __float_as_uint(bb.y);
                #pragma unroll
                for (int mt = 0; mt < 4; mt++)
                    mma8(acc[mt][nt], a[mt], b0, b1);
            }
        }
        __syncthreads();
    }

    const int n0 = blockIdx.x * 128;
    #pragma unroll
    for (int mt = 0; mt < 4; mt++) {
        const int row = m0 + wm * 64 + mt * 16 + gr;
        #pragma unroll
        for (int nt = 0; nt < 4; nt++) {
            const int col = n0 + wn * 32 + nt * 8 + 2 * tc;
            *(float2*)&out[(size_t)row * HVc + col] =
                make_float2(acc[mt][nt][0], acc[mt][nt][1]);
            *(float2*)&out[(size_t)(row + 8) * HVc + col] =
                make_float2(acc[mt][nt][2], acc[mt][nt][3]);
        }
    }
}

extern "C" void kernel_launch(void* const* d_in, const int* in_sizes, int n_in,
                              void* d_out, int out_size)
{
    const float* qpos   = (const float*)d_in[0];
    const float* kpos   = (const float*)d_in[1];
    const float* values = (const float*)d_in[2];
    const int*   mask   = (const int*)  d_in[3];
    const float* ls     = (const float*)d_in[4];
    const float* w_out  = (const float*)d_in[5];
    float* out = (float*)d_out;

    const int smem_bytes = ASMEM_FLOATS * (int)sizeof(float);
    cudaFuncSetAttribute(attend_kernel,
                         cudaFuncAttributeMaxDynamicSharedMemorySize, smem_bytes);

    compact_kernel<<<Bc, 32>>>(mask);
    gather_kernel<<<Bc * 32, NTHREADS>>>(kpos, values);
    prep_w<<<512, 256>>>(w_out);
    attend_kernel<<<Bc * (Lc / 32), NTHREADS, smem_bytes>>>(qpos, ls);
    proj_kernel<<<dim3(HVc / 128, (Bc * Lc) / 128), 256>>>(out);
}

// round 12
// speedup vs baseline: 1.7288x; 1.0457x over previous
#include <cuda_runtime.h>

#define Bc 4
#define Lc 2048
#define Hc 8
#define Vc 64
#define HVc 512
#define NTHREADS 256

__device__ __forceinline__ float to_tf32(float x) {
    float r; asm("cvt.rna.tf32.f32 %0, %1;" : "=f"(r) : "f"(x)); return r;
}
// D += A(m16k8,row) * B(k8n8,col), tf32
__device__ __forceinline__ void mma8(float* d, const unsigned* a,
                                     unsigned b0, unsigned b1) {
    asm("mma.sync.aligned.m16n8k8.row.col.f32.tf32.tf32.f32 "
        "{%0,%1,%2,%3}, {%4,%5,%6,%7}, {%8,%9}, {%0,%1,%2,%3};"
        : "+f"(d[0]), "+f"(d[1]), "+f"(d[2]), "+f"(d[3])
        : "r"(a[0]), "r"(a[1]), "r"(a[2]), "r"(a[3]), "r"(b0), "r"(b1));
}
__device__ __forceinline__ float ex2(float x) {
    float r; asm("ex2.approx.ftz.f32 %0, %1;" : "=f"(r) : "f"(x)); return r;
}

// ---- persistent device scratch ----
__device__ float g_att[Bc * Lc * HVc];          // normalized attended
__device__ float g_vb[Bc * 256 * 64 * 32 * 2];  // V in b-fragment order (tf32)
__device__ float g_wb[64 * 64 * 32 * 2];        // W in b-fragment order (tf32)
__device__ float g_kpos4[Bc * Lc * 4];          // compacted kpos (x,y,z,|k|^2), pad=1000
__device__ int   g_idx[Bc * Lc];
__device__ int   g_cnt[Bc];

// ================= compaction =================
__global__ void compact_kernel(const int* __restrict__ mask)
{
    const int b = blockIdx.x;
    const int lane = threadIdx.x;
    int cnt = 0;
    for (int k0 = 0; k0 < Lc; k0 += 32) {
        const int k = k0 + lane;
        const bool u = (mask[b * Lc + k] == 0);
        const unsigned bal = __ballot_sync(0xFFFFFFFFu, u);
        if (u) {
            const int pos = cnt + __popc(bal & ((1u << lane) - 1u));
            g_idx[b * Lc + pos] = k;
        }
        cnt += __popc(bal);
    }
    if (lane == 0) g_cnt[b] = cnt;
}

// ====== gather: values -> b-fragment layout (tf32); kpos4 with |k|^2 ======
__global__ void gather_kernel(const float* __restrict__ kpos,
                              const float* __restrict__ values)
{
    const int b  = blockIdx.x >> 5;
    const int j0 = (blockIdx.x & 31) * 64;
    const int tid = threadIdx.x;
    __shared__ int s_idx[64];
    __shared__ int s_n[2];

    if (tid == 0) { int c = g_cnt[b]; s_n[0] = c; s_n[1] = (c + 31) & ~31; }
    if (tid < 64 && j0 + tid < Lc) s_idx[tid] = g_idx[b * Lc + j0 + tid];
    __syncthreads();
    const int cnt = s_n[0];
    const int pad = s_n[1];
    const int jend = min(j0 + 64, pad);
    if (jend <= j0) return;
    const int nrows = jend - j0;

    const float4* v4 = (const float4*)values;
    for (int e = tid; e < nrows * 128; e += NTHREADS) {
        const int jl = e >> 7;
        const int c4 = e & 127;
        const int j  = j0 + jl;
        float4 v;
        if (j < cnt) v = v4[(size_t)(b * Lc + s_idx[jl]) * 128 + c4];
        else         v = make_float4(0.f, 0.f, 0.f, 0.f);
        v.x = to_tf32(v.x); v.y = to_tf32(v.y);
        v.z = to_tf32(v.z); v.w = to_tf32(v.w);
        const int ksg = j >> 3, kk = j & 7;
        const int tc = kk & 3, reg = kk >> 2;
        const float* pv = &v.x;
        #pragma unroll
        for (int t = 0; t < 4; t++) {
            const int c = c4 * 4 + t;
            const int h = c >> 6, n = (c >> 3) & 7, gr = c & 7;
            const size_t idx =
                ((((size_t)b * 256 + ksg) * 64 + h * 8 + n) * 32 + gr * 4 + tc) * 2 + reg;
            g_vb[idx] = pv[t];
        }
    }
    for (int jl = tid; jl < nrows; jl += NTHREADS) {
        const int j = j0 + jl;
        float x, y, z;
        if (j < cnt) {
            const float* p = kpos + (size_t)(b * Lc + s_idx[jl]) * 3;
            x = p[0]; y = p[1]; z = p[2];
        } else {
            x = y = z = 1000.0f;
        }
        const float k2 = x * x + y * y + z * z;
        ((float4*)g_kpos4)[(size_t)b * Lc + j] = make_float4(x, y, z, k2);
    }
}

// ====== W prepack: b-fragment order, tf32 ======
__global__ void prep_w(const float* __restrict__ W)
{
    const int p = blockIdx.x * 256 + threadIdx.x;   // float2 slot
    const int tc = p & 3;
    const int gr = (p >> 2) & 7;
    const int nb = (p >> 5) & 63;
    const int kb = p >> 11;
    const int row = nb * 8 + gr;
    const int col = kb * 8 + tc;
    g_wb[2 * p]     = to_tf32(W[row * HVc + col]);
    g_wb[2 * p + 1] = to_tf32(W[row * HVc + col + 4]);
}

// ====== attend: warp-autonomous, zero smem, zero barriers ======
// warp = (b, 32-query tile, head). a-fragments computed in registers:
//   arg(q,k) = Aq + negc*|k|^2 + qs.k  with qs = -2*negc*q  => arg = negc*d^2
// den accumulated per thread (rows gr+8j, k = tc mod 4) + quad shfl reduce.
__global__ __launch_bounds__(128, 4)
void attend_kernel(const float* __restrict__ qpos,
                   const float* __restrict__ ls)
{
    const int lane = threadIdx.x & 31;
    const int warp = threadIdx.x >> 5;
    const int gw = blockIdx.x * 4 + warp;   // 2048 warps total
    const int b  = gw >> 9;
    const int qt = (gw >> 3) & 63;
    const int h  = gw & 7;
    const int gr = lane >> 2;
    const int tc = lane & 3;

    const float l = ls[h];
    const float negc = -1.4426950408889634f / (l * l);   // -log2(e)/ls^2

    float qsx[4], qsy[4], qsz[4], Aq[4];
    #pragma unroll
    for (int j = 0; j < 4; j++) {
        const int q = qt * 32 + gr + 8 * j;
        const float* qp = qpos + (size_t)(b * Lc + q) * 3;
        const float x = qp[0], y = qp[1], z = qp[2];
        Aq[j]  = negc * (x * x + y * y + z * z);
        qsx[j] = -2.0f * negc * x;     // FIX: cross term is -2 q.k inside d^2
        qsy[j] = -2.0f * negc * y;
        qsz[j] = -2.0f * negc * z;
    }

    const int nt = ((g_cnt[b] + 31) & ~31) >> 5;

    float acc[2][8][4];
    #pragma unroll
    for (int m = 0; m < 2; m++)
        #pragma unroll
        for (int n = 0; n < 8; n++)
            #pragma unroll
            for (int r = 0; r < 4; r++) acc[m][n][r] = 0.0f;
    float denp[4] = {0.0f, 0.0f, 0.0f, 0.0f};

    const float4* kp4 = (const float4*)g_kpos4 + (size_t)b * Lc;
    const float2* vpw = (const float2*)g_vb +
                        (((size_t)b * 256) * 64 + h * 8) * 32 + lane;

    for (int t = 0; t < nt; t++) {
        #pragma unroll
        for (int ks = 0; ks < 4; ks++) {
            const int kb0 = t * 32 + ks * 8;
            const float4 ka = kp4[kb0 + tc];
            const float4 kc2 = kp4[kb0 + tc + 4];

            float ea[4], eb[4];
            #pragma unroll
            for (int j = 0; j < 4; j++) {
                float arg = fmaf(negc, ka.w, Aq[j]);
                arg = fmaf(qsx[j], ka.x, arg);
                arg = fmaf(qsy[j], ka.y, arg);
                arg = fmaf(qsz[j], ka.z, arg);
                ea[j] = ex2(arg);
                denp[j] += ea[j];
            }
            #pragma unroll
            for (int j = 0; j < 4; j++) {
                float arg = fmaf(negc, kc2.w, Aq[j]);
                arg = fmaf(qsx[j], kc2.x, arg);
                arg = fmaf(qsy[j], kc2.y, arg);
                arg = fmaf(qsz[j], kc2.z, arg);
                eb[j] = ex2(arg);
                denp[j] += eb[j];
            }

            unsigned a0[4], a1[4];
            a0[0] = __float_as_uint(to_tf32(ea[0]));
            a0[1] = __float_as_uint(to_tf32(ea[1]));
            a0[2] = __float_as_uint(to_tf32(eb[0]));
            a0[3] = __float_as_uint(to_tf32(eb[1]));
            a1[0] = __float_as_uint(to_tf32(ea[2]));
            a1[1] = __float_as_uint(to_tf32(ea[3]));
            a1[2] = __float_as_uint(to_tf32(eb[2]));
            a1[3] = __float_as_uint(to_tf32(eb[3]));

            const float2* vp = vpw + ((size_t)t * 4 + ks) * (64 * 32);
            #pragma unroll
            for (int n = 0; n < 8; n++) {
                const float2 bb = vp[n * 32];
                const unsigned b0 = __float_as_uint(bb.x);
                const unsigned b1 = __float_as_uint(bb.y);
                mma8(acc[0][n], a0, b0, b1);
                mma8(acc[1][n], a1, b0, b1);
            }
        }
    }

    // den: reduce across the quad (lanes sharing gr, tc = 0..3)
    #pragma unroll
    for (int j = 0; j < 4; j++) {
        denp[j] += __shfl_xor_sync(0xFFFFFFFFu, denp[j], 1);
        denp[j] += __shfl_xor_sync(0xFFFFFFFFu, denp[j], 2);
    }

    // epilogue: normalize + write
    #pragma unroll
    for (int m = 0; m < 2; m++) {
        const float i0 = 1.0f / (denp[2 * m] + 1e-5f);       // row gr + 16m
        const float i1 = 1.0f / (denp[2 * m + 1] + 1e-5f);   // row gr + 8 + 16m
        const int q0 = qt * 32 + m * 16 + gr;
        const size_t rb = (size_t)(b * Lc + q0) * HVc + h * 64 + 2 * tc;
        #pragma unroll
        for (int n = 0; n < 8; n++) {
            *(float2*)&g_att[rb + n * 8] =
                make_float2(acc[m][n][0] * i0, acc[m][n][1] * i0);
            *(float2*)&g_att[rb + 8 * HVc + n * 8] =
                make_float2(acc[m][n][2] * i1, acc[m][n][3] * i1);
        }
    }
}

// ====== projection (unchanged): tf32 mma, 128x128 tile, W from g_wb ======
#define ASTRIDE 20   // 16 k + pad 4 -> bank(m-frag) = (20*gr+tc)%32, all distinct

__global__ __launch_bounds__(256, 2)
void proj_kernel(float* __restrict__ out)
{
    __shared__ float As[128 * ASTRIDE];   // [m][k] for current 16-k chunk

    const int tid = threadIdx.x;
    const int lane = tid & 31;
    const int warp = tid >> 5;
    const int gr = lane >> 2;
    const int tc = lane & 3;
    const int wm = warp & 1;       // 2 m-halves of 64
    const int wn = warp >> 1;      // 4 n-quarters of 32
    const int m0 = blockIdx.y * 128;

    const int row0 = tid >> 2;           // 0..63
    const int row1 = 64 + row0;
    const int cg   = (tid & 3) * 4;      // k sub-group within chunk

    float acc[4][4][4];
    #pragma unroll
    for (int mt = 0; mt < 4; mt++)
        #pragma unroll
        for (int nt = 0; nt < 4; nt++)
            #pragma unroll
            for (int r = 0; r < 4; r++) acc[mt][nt][r] = 0.0f;

    const float4* att4 = (const float4*)g_att;
    const float2* wb2 = (const float2*)g_wb;

    float4 r0 = att4[(size_t)(m0 + row0) * 128 + (cg >> 2)];
    float4 r1 = att4[(size_t)(m0 + row1) * 128 + (cg >> 2)];

    for (int k0 = 0; k0 < HVc; k0 += 16) {
        As[row0 * ASTRIDE + cg + 0] = to_tf32(r0.x);
        As[row0 * ASTRIDE + cg + 1] = to_tf32(r0.y);
        As[row0 * ASTRIDE + cg + 2] = to_tf32(r0.z);
        As[row0 * ASTRIDE + cg + 3] = to_tf32(r0.w);
        As[row1 * ASTRIDE + cg + 0] = to_tf32(r1.x);
        As[row1 * ASTRIDE + cg + 1] = to_tf32(r1.y);
        As[row1 * ASTRIDE + cg + 2] = to_tf32(r1.z);
        As[row1 * ASTRIDE + cg + 3] = to_tf32(r1.w);
        __syncthreads();

        if (k0 + 16 < HVc) {
            const int kn = (k0 + 16 + cg) >> 2;
            r0 = att4[(size_t)(m0 + row0) * 128 + kn];
            r1 = att4[(size_t)(m0 + row1) * 128 + kn];
        }

        #pragma unroll
        for (int kk = 0; kk < 2; kk++) {
            const int kc = kk * 8 + tc;
            unsigned a[4][4];
            #pragma unroll
            for (int mt = 0; mt < 4; mt++) {
                const int mr = wm * 64 + mt * 16 + gr;
                a[mt][0] = __float_as_uint(As[mr * ASTRIDE + kc]);
                a[mt][1] = __float_as_uint(As[(mr + 8) * ASTRIDE + kc]);
                a[mt][2] = __float_as_uint(As[mr * ASTRIDE + kc + 4]);
                a[mt][3] = __float_as_uint(As[(mr + 8) * ASTRIDE + kc + 4]);
            }
            const int kb = (k0 >> 3) + kk;
            const int nbase = blockIdx.x * 16 + wn * 4;
            #pragma unroll
            for (int nt = 0; nt < 4; nt++) {
                const float2 bb = wb2[(size_t)(kb * 64 + nbase + nt) * 32 + lane];
                const unsigned b0 = __float_as_uint(bb.x);
                const unsigned b1 = __float_as_uint(bb.y);
                #pragma unroll
                for (int mt = 0; mt < 4; mt++)
                    mma8(acc[mt][nt], a[mt], b0, b1);
            }
        }
        __syncthreads();
    }

    const int n0 = blockIdx.x * 128;
    #pragma unroll
    for (int mt = 0; mt < 4; mt++) {
        const int row = m0 + wm * 64 + mt * 16 + gr;
        #pragma unroll
        for (int nt = 0; nt < 4; nt++) {
            const int col = n0 + wn * 32 + nt * 8 + 2 * tc;
            *(float2*)&out[(size_t)row * HVc + col] =
                make_float2(acc[mt][nt][0], acc[mt][nt][1]);
            *(float2*)&out[(size_t)(row + 8) * HVc + col] =
                make_float2(acc[mt][nt][2], acc[mt][nt][3]);
        }
    }
}

extern "C" void kernel_launch(void* const* d_in, const int* in_sizes, int n_in,
                              void* d_out, int out_size)
{
    const float* qpos   = (const float*)d_in[0];
    const float* kpos   = (const float*)d_in[1];
    const float* values = (const float*)d_in[2];
    const int*   mask   = (const int*)  d_in[3];
    const float* ls     = (const float*)d_in[4];
    const float* w_out  = (const float*)d_in[5];
    float* out = (float*)d_out;

    compact_kernel<<<Bc, 32>>>(mask);
    gather_kernel<<<Bc * 32, NTHREADS>>>(kpos, values);
    prep_w<<<512, 256>>>(w_out);
    attend_kernel<<<512, 128>>>(qpos, ls);
    proj_kernel<<<dim3(HVc / 128, (Bc * Lc) / 128), 256>>>(out);
}